// round 7
// baseline (speedup 1.0000x reference)
#include <cuda_runtime.h>

#define N_MAX 50000
#define E_MAX 800000
#define IN_FEATS 128
#define HF 64

// Scratch (device globals; no allocation allowed)
__device__ int   g_cnt[N_MAX];
__device__ int   g_off[N_MAX + 1];
__device__ int   g_cur[N_MAX];
__device__ int   g_bsum[256];
__device__ int   g_esrc[E_MAX];
__device__ float g_dinv[N_MAX];
__device__ float g_x[N_MAX * HF];
__device__ float g_f1[N_MAX * HF];
__device__ float g_f2[N_MAX * HF];

// ---------------------------------------------------------------------------
__global__ void zero_cnt_kernel(int n) {
    int i = blockIdx.x * blockDim.x + threadIdx.x;
    if (i < n) g_cnt[i] = 0;
}

__global__ void count_kernel(const int* __restrict__ dst, int e) {
    int i = blockIdx.x * blockDim.x + threadIdx.x;
    if (i < e) atomicAdd(&g_cnt[dst[i]], 1);
}

// ---- scan stage 1: per-block exclusive scan of g_cnt, block sums -> g_bsum --
__global__ void scan1_kernel(int n) {
    __shared__ int sh[256];
    int t = threadIdx.x;
    int i = blockIdx.x * 256 + t;
    int v = (i < n) ? g_cnt[i] : 0;
    sh[t] = v;
    __syncthreads();
#pragma unroll
    for (int o = 1; o < 256; o <<= 1) {
        int add = (t >= o) ? sh[t - o] : 0;
        __syncthreads();
        sh[t] += add;
        __syncthreads();
    }
    if (i < n) g_off[i] = sh[t] - v;
    if (t == 255) g_bsum[blockIdx.x] = sh[255];
}

// ---- scan stage 2 (fused): each block scans g_bsum itself, then finalizes
//      offsets, g_cur, and dinv. Removes the old single-block scan2 launch. ---
__global__ void scan3_kernel(int n, int e, int nb) {
    __shared__ int sh[256];
    int t = threadIdx.x;
    sh[t] = (t < nb) ? g_bsum[t] : 0;
    __syncthreads();
#pragma unroll
    for (int o = 1; o < 256; o <<= 1) {
        int add = (t >= o) ? sh[t - o] : 0;
        __syncthreads();
        sh[t] += add;
        __syncthreads();
    }
    int boff = (blockIdx.x == 0) ? 0 : sh[blockIdx.x - 1];
    int i = blockIdx.x * 256 + t;
    if (i < n) {
        int o = g_off[i] + boff;
        g_off[i] = o;
        g_cur[i] = o;
        g_dinv[i] = rsqrtf(fmaxf((float)g_cnt[i], 1.0f));
    }
    if (i == 0) g_off[n] = e;
}

__global__ void fill_kernel(const int* __restrict__ src,
                            const int* __restrict__ dst, int e) {
    int i = blockIdx.x * blockDim.x + threadIdx.x;
    if (i < e) {
        int d = dst[i];
        int pos = atomicAdd(&g_cur[d], 1);
        g_esrc[pos] = src[i];
    }
}

// ---------------------------------------------------------------------------
// Gather SpMM: fout[d] = fin[d] - dinv[d] * sum_{s in N(d)} dinv[s]*fin[s]
// One warp per dst node; 16 lanes per edge (float4), each half-warp runs an
// independent edge stream with 2 accumulators and 2-ahead index prefetch
// => 4 outstanding feature LDG.128 per warp.
// step 0: g_x -> g_f1;  step 1: g_f1 -> g_f2.
__global__ __launch_bounds__(256) void spmm_kernel(int n, int step) {
    const float* fin = (step == 0) ? g_x : g_f1;
    float* fout      = (step == 0) ? g_f1 : g_f2;
    int w = (blockIdx.x * blockDim.x + threadIdx.x) >> 5;
    int lane = threadIdx.x & 31;
    if (w >= n) return;
    int c = lane & 15;        // float4 column 0..15
    int half = lane >> 4;     // 0 or 1: which edge stream
    int beg = g_off[w];
    int end = g_off[w + 1];
    const float4* F4 = reinterpret_cast<const float4*>(fin);
    float4 acc1 = make_float4(0.f, 0.f, 0.f, 0.f);
    float4 acc2 = make_float4(0.f, 0.f, 0.f, 0.f);

    int j = beg + half;       // this stream handles j, j+2, j+4, ...
    int sA = (j < end)     ? __ldg(&g_esrc[j])     : 0;
    int sB = (j + 2 < end) ? __ldg(&g_esrc[j + 2]) : 0;
    while (j + 2 < end) {     // both sA (j) and sB (j+2) valid
        float wA = __ldg(&g_dinv[sA]);
        float4 vA = F4[(size_t)sA * 16 + c];
        float wB = __ldg(&g_dinv[sB]);
        float4 vB = F4[(size_t)sB * 16 + c];
        int jn = j + 4;
        sA = (jn < end)     ? __ldg(&g_esrc[jn])     : 0;
        sB = (jn + 2 < end) ? __ldg(&g_esrc[jn + 2]) : 0;
        acc1.x = fmaf(wA, vA.x, acc1.x);
        acc1.y = fmaf(wA, vA.y, acc1.y);
        acc1.z = fmaf(wA, vA.z, acc1.z);
        acc1.w = fmaf(wA, vA.w, acc1.w);
        acc2.x = fmaf(wB, vB.x, acc2.x);
        acc2.y = fmaf(wB, vB.y, acc2.y);
        acc2.z = fmaf(wB, vB.z, acc2.z);
        acc2.w = fmaf(wB, vB.w, acc2.w);
        j = jn;
    }
    if (j < end) {            // one leftover edge in this stream (index sA)
        float wt = __ldg(&g_dinv[sA]);
        float4 v = F4[(size_t)sA * 16 + c];
        acc1.x = fmaf(wt, v.x, acc1.x);
        acc1.y = fmaf(wt, v.y, acc1.y);
        acc1.z = fmaf(wt, v.z, acc1.z);
        acc1.w = fmaf(wt, v.w, acc1.w);
    }
    acc1.x += acc2.x; acc1.y += acc2.y; acc1.z += acc2.z; acc1.w += acc2.w;

    // cross-half reduction: lanes L and L^16 hold partials for chunk c
    acc1.x += __shfl_xor_sync(0xffffffffu, acc1.x, 16);
    acc1.y += __shfl_xor_sync(0xffffffffu, acc1.y, 16);
    acc1.z += __shfl_xor_sync(0xffffffffu, acc1.z, 16);
    acc1.w += __shfl_xor_sync(0xffffffffu, acc1.w, 16);

    if (half == 0) {
        float wd = g_dinv[w];
        float4 xv = F4[(size_t)w * 16 + c];
        float4 r = make_float4(xv.x - wd * acc1.x, xv.y - wd * acc1.y,
                               xv.z - wd * acc1.z, xv.w - wd * acc1.w);
        reinterpret_cast<float4*>(fout)[(size_t)w * 16 + c] = r;
    }
}

// ---------------------------------------------------------------------------
// GEMM1: g_x = relu(features[n,128] @ W1[64,128]^T + b1)
// 256 threads, M-tile 128, N=64, 4x8 per thread. Software-pipelined: next
// k-chunk's global loads are issued into registers while FMAs run.
__global__ __launch_bounds__(256) void gemm1_kernel(
    const float* __restrict__ A, const float* __restrict__ W1,
    const float* __restrict__ b1, int n) {
    __shared__ float As[32][132];
    __shared__ float Bs[32][68];
    int t = threadIdx.x;
    int m0 = blockIdx.x * 128;
    int tx = t & 7, ty = t >> 3;
    int kv = t & 7, m4 = t >> 3;

    float acc[4][8];
#pragma unroll
    for (int i = 0; i < 4; i++)
#pragma unroll
        for (int j = 0; j < 8; j++) acc[i][j] = 0.f;

    float4 pa[4], pb[2];
    // preload chunk 0
#pragma unroll
    for (int i = 0; i < 4; i++) {
        int gm = m0 + m4 * 4 + i;
        pa[i] = make_float4(0.f, 0.f, 0.f, 0.f);
        if (gm < n)
            pa[i] = *reinterpret_cast<const float4*>(A + (size_t)gm * IN_FEATS + kv * 4);
    }
#pragma unroll
    for (int i = 0; i < 2; i++) {
        int fl = t * 2 + i;
        int nn = fl >> 3, kv2 = fl & 7;
        pb[i] = *reinterpret_cast<const float4*>(W1 + (size_t)nn * IN_FEATS + kv2 * 4);
    }

#pragma unroll
    for (int ch = 0; ch < 4; ch++) {
        // stage current chunk into smem
#pragma unroll
        for (int i = 0; i < 4; i++) {
            int m = m4 * 4 + i;
            As[kv * 4 + 0][m] = pa[i].x;
            As[kv * 4 + 1][m] = pa[i].y;
            As[kv * 4 + 2][m] = pa[i].z;
            As[kv * 4 + 3][m] = pa[i].w;
        }
#pragma unroll
        for (int i = 0; i < 2; i++) {
            int fl = t * 2 + i;
            int nn = fl >> 3, kv2 = fl & 7;
            Bs[kv2 * 4 + 0][nn] = pb[i].x;
            Bs[kv2 * 4 + 1][nn] = pb[i].y;
            Bs[kv2 * 4 + 2][nn] = pb[i].z;
            Bs[kv2 * 4 + 3][nn] = pb[i].w;
        }
        __syncthreads();
        // issue next chunk's global loads (overlap with FMA below)
        if (ch < 3) {
            int k0 = (ch + 1) * 32;
#pragma unroll
            for (int i = 0; i < 4; i++) {
                int gm = m0 + m4 * 4 + i;
                pa[i] = make_float4(0.f, 0.f, 0.f, 0.f);
                if (gm < n)
                    pa[i] = *reinterpret_cast<const float4*>(A + (size_t)gm * IN_FEATS + k0 + kv * 4);
            }
#pragma unroll
            for (int i = 0; i < 2; i++) {
                int fl = t * 2 + i;
                int nn = fl >> 3, kv2 = fl & 7;
                pb[i] = *reinterpret_cast<const float4*>(W1 + (size_t)nn * IN_FEATS + k0 + kv2 * 4);
            }
        }
#pragma unroll
        for (int k = 0; k < 32; k++) {
            float4 a = *reinterpret_cast<float4*>(&As[k][ty * 4]);
            float4 bA = *reinterpret_cast<float4*>(&Bs[k][tx * 8]);
            float4 bB = *reinterpret_cast<float4*>(&Bs[k][tx * 8 + 4]);
            float av[4] = {a.x, a.y, a.z, a.w};
            float bv[8] = {bA.x, bA.y, bA.z, bA.w, bB.x, bB.y, bB.z, bB.w};
#pragma unroll
            for (int i = 0; i < 4; i++)
#pragma unroll
                for (int j = 0; j < 8; j++)
                    acc[i][j] = fmaf(av[i], bv[j], acc[i][j]);
        }
        __syncthreads();
    }
#pragma unroll
    for (int i = 0; i < 4; i++) {
        int gm = m0 + ty * 4 + i;
        if (gm < n) {
#pragma unroll
            for (int j = 0; j < 8; j++) {
                float v = acc[i][j] + b1[tx * 8 + j];
                g_x[(size_t)gm * HF + tx * 8 + j] = v > 0.f ? v : 0.f;
            }
        }
    }
}

// ---------------------------------------------------------------------------
// GEMM2: out = [x | f1 | f2] @ M^T + b2   (K=192), where M = theta-fold of W2
// is computed ON THE FLY in the B-tile loader (no buildM kernel / g_M buffer).
// M[r][k] with k = p*64+c:  cA[p]*W2[r][c] + cB[p]*W2[r][64+c] + cC[p]*W2[r][128+c]
__global__ __launch_bounds__(256) void gemm2_kernel(
    const float* __restrict__ W2, const float* __restrict__ b2,
    float* __restrict__ out, int n) {
    __shared__ float As[32][132];
    __shared__ float Bs[32][68];
    int t = threadIdx.x;
    int m0 = blockIdx.x * 128;
    int tx = t & 7, ty = t >> 3;
    int kv = t & 7, m4 = t >> 3;

    float acc[4][8];
#pragma unroll
    for (int i = 0; i < 4; i++)
#pragma unroll
        for (int j = 0; j < 8; j++) acc[i][j] = 0.f;

#pragma unroll
    for (int cch = 0; cch < 6; cch++) {
        const float* S = (cch < 2) ? g_x : (cch < 4) ? g_f1 : g_f2;
        int koff = (cch & 1) * 32;
#pragma unroll
        for (int i = 0; i < 4; i++) {
            int m = m4 * 4 + i;
            int gm = m0 + m;
            float4 v = make_float4(0.f, 0.f, 0.f, 0.f);
            if (gm < n)
                v = *reinterpret_cast<const float4*>(S + (size_t)gm * HF + koff + kv * 4);
            As[kv * 4 + 0][m] = v.x;
            As[kv * 4 + 1][m] = v.y;
            As[kv * 4 + 2][m] = v.z;
            As[kv * 4 + 3][m] = v.w;
        }
#pragma unroll
        for (int i = 0; i < 2; i++) {
            int fl = t * 2 + i;
            int nn = fl >> 3, kv2 = fl & 7;
            int kk = cch * 32 + kv2 * 4;      // global K index (0..188, mult of 4)
            int p = kk >> 6;                  // constant across the float4
            int c0 = kk & 63;
            float ca = (p == 0) ? 3.0f  : (p == 1) ? -3.0f : 0.75f;
            float cb = (p == 0) ? 0.0f  : (p == 1) ?  3.0f : -1.5f;
            float cc = (p == 2) ? 0.75f : 0.0f;
            const float* wrow = W2 + (size_t)nn * 192;
            float4 wa = *reinterpret_cast<const float4*>(wrow + c0);
            float4 wb = *reinterpret_cast<const float4*>(wrow + 64 + c0);
            float4 wc = *reinterpret_cast<const float4*>(wrow + 128 + c0);
            Bs[kv2 * 4 + 0][nn] = ca * wa.x + cb * wb.x + cc * wc.x;
            Bs[kv2 * 4 + 1][nn] = ca * wa.y + cb * wb.y + cc * wc.y;
            Bs[kv2 * 4 + 2][nn] = ca * wa.z + cb * wb.z + cc * wc.z;
            Bs[kv2 * 4 + 3][nn] = ca * wa.w + cb * wb.w + cc * wc.w;
        }
        __syncthreads();
#pragma unroll
        for (int k = 0; k < 32; k++) {
            float4 a = *reinterpret_cast<float4*>(&As[k][ty * 4]);
            float4 bA = *reinterpret_cast<float4*>(&Bs[k][tx * 8]);
            float4 bB = *reinterpret_cast<float4*>(&Bs[k][tx * 8 + 4]);
            float av[4] = {a.x, a.y, a.z, a.w};
            float bv[8] = {bA.x, bA.y, bA.z, bA.w, bB.x, bB.y, bB.z, bB.w};
#pragma unroll
            for (int i = 0; i < 4; i++)
#pragma unroll
                for (int j = 0; j < 8; j++)
                    acc[i][j] = fmaf(av[i], bv[j], acc[i][j]);
        }
        __syncthreads();
    }
#pragma unroll
    for (int i = 0; i < 4; i++) {
        int gm = m0 + ty * 4 + i;
        if (gm < n) {
#pragma unroll
            for (int j = 0; j < 8; j++)
                out[(size_t)gm * HF + tx * 8 + j] = acc[i][j] + b2[tx * 8 + j];
        }
    }
}

// ---------------------------------------------------------------------------
extern "C" void kernel_launch(void* const* d_in, const int* in_sizes, int n_in,
                              void* d_out, int out_size) {
    const float* features = (const float*)d_in[0];
    const int*   src      = (const int*)d_in[1];
    const int*   dst      = (const int*)d_in[2];
    const float* W1       = (const float*)d_in[3];
    const float* b1       = (const float*)d_in[4];
    const float* W2       = (const float*)d_in[5];
    const float* b2       = (const float*)d_in[6];
    float* out = (float*)d_out;

    int n = in_sizes[0] / IN_FEATS;   // 50000
    int e = in_sizes[1];              // 800000
    int nb = (n + 255) / 256;         // 196

    zero_cnt_kernel<<<nb, 256>>>(n);
    count_kernel<<<(e + 255) / 256, 256>>>(dst, e);
    scan1_kernel<<<nb, 256>>>(n);
    scan3_kernel<<<nb, 256>>>(n, e, nb);
    fill_kernel<<<(e + 255) / 256, 256>>>(src, dst, e);

    gemm1_kernel<<<(n + 127) / 128, 256>>>(features, W1, b1, n);

    int spmm_blocks = (n + 7) / 8;    // 8 warps/block, warp per node
    spmm_kernel<<<spmm_blocks, 256>>>(n, 0);
    spmm_kernel<<<spmm_blocks, 256>>>(n, 1);

    gemm2_kernel<<<(n + 127) / 128, 256>>>(W2, b2, out, n);
}